// round 17
// baseline (speedup 1.0000x reference)
#include <cuda_runtime.h>
#include <cstdint>

#define NN   100000
#define TT   10
#define FF   64
#define EE   1600000
#define EDD  8
#define HH   128
#define BB   2048
#define CC   2
#define BN_EPS 1e-5f

// ---------------- device scratch ----------------
__device__ __align__(16) float g_wcomb[128 * 128];             // [k][h] fp32 (focal)
__device__ __align__(16) float g_wT_hi[128 * 128];             // [h][k] tf32-hi
__device__ __align__(16) float g_wT_lo[128 * 128];             // [h][k] tf32-lo
__device__ __align__(16) float g_wlstm[256 * 512];
__device__ __align__(16) float g_static[(size_t)NN * HH];      // [n][h] (focal)
__device__ __align__(16) float g_staticT[(size_t)HH * NN];     // [h][n] (sage epilogue)
__device__ __align__(16) float g_eattr[NN * EDD];
__device__ __align__(16) float g_agg[(size_t)NN * TT * FF];    // [n][t][64]
__device__ int   g_deg[NN];
__device__ int   g_rowoff[NN + 1];
__device__ int   g_cursor[NN];
__device__ int   g_csr_src[EE];
__device__ float g_stats_t[TT * 2 * HH];
__device__ __align__(16) float g_hseq[(size_t)TT * BB * HH];
__device__ __align__(16) float g_h[BB * HH];
__device__ __align__(16) float g_c[BB * HH];

// ---------------- helpers ----------------
__device__ __forceinline__ unsigned long long pk2(float a, float b) {
    unsigned long long r;
    asm("mov.b64 %0, {%1, %2};" : "=l"(r) : "f"(a), "f"(b));
    return r;
}
__device__ __forceinline__ unsigned long long ffma2(unsigned long long a, unsigned long long b,
                                                    unsigned long long c) {
    unsigned long long d;
    asm("fma.rn.f32x2 %0, %1, %2, %3;" : "=l"(d) : "l"(a), "l"(b), "l"(c));
    return d;
}
__device__ __forceinline__ void upk2(unsigned long long v, float& a, float& b) {
    asm("mov.b64 {%0, %1}, %2;" : "=f"(a), "=f"(b) : "l"(v));
}
__device__ __forceinline__ float tf32r(float x) {
    float r;
    asm("cvt.rna.tf32.f32 %0, %1;" : "=f"(r) : "f"(x));
    return r;
}
__device__ __forceinline__ void mma_tf32(float* d, const unsigned* a, const unsigned* b) {
    asm("mma.sync.aligned.m16n8k8.row.col.f32.tf32.tf32.f32 "
        "{%0,%1,%2,%3}, {%4,%5,%6,%7}, {%8,%9}, {%0,%1,%2,%3};"
        : "+f"(d[0]), "+f"(d[1]), "+f"(d[2]), "+f"(d[3])
        : "r"(a[0]), "r"(a[1]), "r"(a[2]), "r"(a[3]), "r"(b[0]), "r"(b[1]));
}

// ---------------- prep ----------------
__global__ void edge_prep_kernel(const int* __restrict__ ei, const float* __restrict__ eattr) {
    int e = blockIdx.x * 256 + threadIdx.x;   // grid = E exactly
    int d = ei[EE + e];
    atomicAdd(&g_deg[d], 1);
    const float4* p = (const float4*)(eattr + (size_t)e * EDD);
    float4 a = p[0], b = p[1];
    float* dst = &g_eattr[d * EDD];
    atomicAdd(dst + 0, a.x); atomicAdd(dst + 1, a.y);
    atomicAdd(dst + 2, a.z); atomicAdd(dst + 3, a.w);
    atomicAdd(dst + 4, b.x); atomicAdd(dst + 5, b.y);
    atomicAdd(dst + 6, b.z); atomicAdd(dst + 7, b.w);
}

__global__ void scan_kernel() {  // 1 block, 1024 threads
    const int CH = (NN + 1023) / 1024;  // 98
    int t = threadIdx.x;
    int beg = t * CH;
    int end = min(beg + CH, NN);
    int s = 0;
    for (int i = beg; i < end; i++) s += g_deg[i];
    __shared__ int ps[1024];
    ps[t] = s;
    __syncthreads();
    for (int off = 1; off < 1024; off <<= 1) {
        int v = (t >= off) ? ps[t - off] : 0;
        __syncthreads();
        ps[t] += v;
        __syncthreads();
    }
    int run = ps[t] - s;
    for (int i = beg; i < end; i++) { g_rowoff[i] = run; run += g_deg[i]; }
    if (t == 1023) g_rowoff[NN] = ps[1023];
}

__global__ void fill_kernel(const int* __restrict__ ei) {
    int e = blockIdx.x * 256 + threadIdx.x;  // grid = E exactly
    int d = ei[EE + e];
    int pos = g_rowoff[d] + atomicAdd(&g_cursor[d], 1);
    g_csr_src[pos] = ei[e];
}

__global__ void static_kernel(const float* __restrict__ w_msg, const float* __restrict__ b_msg,
                              const float* __restrict__ b_self) {
    int idx = blockIdx.x * 256 + threadIdx.x;  // grid = N*H exactly
    int n = idx >> 7, h = idx & 127;
    int dg = g_deg[n];
    float s = 0.f;
#pragma unroll
    for (int j = 0; j < EDD; j++)
        s += g_eattr[n * EDD + j] * w_msg[(FF + j) * HH + h];
    float inv = 1.f / (float)max(dg, 1);
    float val = b_self[h] + (s + (float)dg * b_msg[h]) * inv;
    g_static[idx] = val;
    g_staticT[(size_t)h * NN + n] = val;
}

__global__ void wcomb_kernel(const float* __restrict__ w_self, const float* __restrict__ w_msg) {
    int idx = blockIdx.x * 256 + threadIdx.x;  // 16384
    int k = idx >> 7, h = idx & 127;
    float w = (k < FF) ? w_self[k * HH + h] : w_msg[(k - FF) * HH + h];
    g_wcomb[idx] = w;
    float hi = tf32r(w);
    float lo = tf32r(w - hi);
    g_wT_hi[h * 128 + k] = hi;
    g_wT_lo[h * 128 + k] = lo;
}

__global__ void wlstm_kernel(const float* __restrict__ w_ih, const float* __restrict__ w_hh) {
    int idx = blockIdx.x * 256 + threadIdx.x;  // 131072
    int k = idx >> 9, j = idx & 511;
    g_wlstm[idx] = (k < HH) ? w_ih[j * HH + k] : w_hh[j * HH + (k - HH)];
}

// ---------------- gather for 5 time-steps (launch twice: tc=0, tc=5) ----------------
__global__ __launch_bounds__(256)
void gather5_kernel(const float* __restrict__ x, int tc) {
    int warp = threadIdx.x >> 5, lane = threadIdx.x & 31;
    int n = blockIdx.x * 8 + warp;
    int half = lane >> 4;
    int fl = (lane & 15) << 2;
    int beg = g_rowoff[n], end = g_rowoff[n + 1];
    const float* xb = x + tc * FF + fl;

    float4 a0 = make_float4(0.f, 0.f, 0.f, 0.f);
    float4 a1 = a0, a2 = a0, a3 = a0, a4 = a0;
    for (int e = beg + half; e < end; e += 2) {
        int src = g_csr_src[e];
        const float4* p = (const float4*)(xb + (size_t)src * (TT * FF));
        float4 v0 = p[0];
        float4 v1 = p[16];
        float4 v2 = p[32];
        float4 v3 = p[48];
        float4 v4 = p[64];
        a0.x += v0.x; a0.y += v0.y; a0.z += v0.z; a0.w += v0.w;
        a1.x += v1.x; a1.y += v1.y; a1.z += v1.z; a1.w += v1.w;
        a2.x += v2.x; a2.y += v2.y; a2.z += v2.z; a2.w += v2.w;
        a3.x += v3.x; a3.y += v3.y; a3.z += v3.z; a3.w += v3.w;
        a4.x += v4.x; a4.y += v4.y; a4.z += v4.z; a4.w += v4.w;
    }
#define RED(f) f = f + __shfl_xor_sync(0xffffffffu, f, 16)
    RED(a0.x); RED(a0.y); RED(a0.z); RED(a0.w);
    RED(a1.x); RED(a1.y); RED(a1.z); RED(a1.w);
    RED(a2.x); RED(a2.y); RED(a2.z); RED(a2.w);
    RED(a3.x); RED(a3.y); RED(a3.z); RED(a3.w);
    RED(a4.x); RED(a4.y); RED(a4.z); RED(a4.w);
#undef RED
    if (half == 0) {
        float inv = 1.f / (float)max(end - beg, 1);
        float* ob = &g_agg[(size_t)n * (TT * FF) + tc * FF + fl];
        *(float4*)(ob +   0) = make_float4(a0.x * inv, a0.y * inv, a0.z * inv, a0.w * inv);
        *(float4*)(ob +  64) = make_float4(a1.x * inv, a1.y * inv, a1.z * inv, a1.w * inv);
        *(float4*)(ob + 128) = make_float4(a2.x * inv, a2.y * inv, a2.z * inv, a2.w * inv);
        *(float4*)(ob + 192) = make_float4(a3.x * inv, a3.y * inv, a3.z * inv, a3.w * inv);
        *(float4*)(ob + 256) = make_float4(a4.x * inv, a4.y * inv, a4.z * inv, a4.w * inv);
    }
}

// ---------------- SAGE via tensor cores: tf32 3-GEMM split + BN stats ----------------
// grid (1563, 10), 256 threads. A = W^T (M=128 ch), B = As (K=128 x N=64 nodes).
#define AS_STR 68

__global__ __launch_bounds__(256)
void sage_tc_kernel(const float* __restrict__ x) {
    extern __shared__ float smem[];
    float* As_hi = smem;                    // [128][AS_STR]
    float* As_lo = smem + 128 * AS_STR;
    float* st    = smem + 2 * 128 * AS_STR; // [256]
    int tid = threadIdx.x;
    int t = blockIdx.y;
    int base = blockIdx.x * 64;
    st[tid] = 0.f;

    // stage x_t and agg_t, split into tf32 hi/lo. thread -> (node nl, quarter q)
    {
        int nl = tid >> 2, q = tid & 3;
        int n = base + nl;
        if (n < NN) {
            const float4* xr = (const float4*)(x + (size_t)n * (TT * FF) + t * FF + q * 16);
            const float4* ar = (const float4*)(g_agg + (size_t)n * (TT * FF) + t * FF + q * 16);
#pragma unroll
            for (int j = 0; j < 4; j++) {
                float4 v = xr[j];
                int k = q * 16 + j * 4;
                float vv[4] = {v.x, v.y, v.z, v.w};
#pragma unroll
                for (int c = 0; c < 4; c++) {
                    float hi = tf32r(vv[c]);
                    As_hi[(k + c) * AS_STR + nl] = hi;
                    As_lo[(k + c) * AS_STR + nl] = tf32r(vv[c] - hi);
                }
            }
#pragma unroll
            for (int j = 0; j < 4; j++) {
                float4 v = ar[j];
                int k = 64 + q * 16 + j * 4;
                float vv[4] = {v.x, v.y, v.z, v.w};
#pragma unroll
                for (int c = 0; c < 4; c++) {
                    float hi = tf32r(vv[c]);
                    As_hi[(k + c) * AS_STR + nl] = hi;
                    As_lo[(k + c) * AS_STR + nl] = tf32r(vv[c] - hi);
                }
            }
        } else {
#pragma unroll
            for (int j = 0; j < 16; j++) {
                As_hi[(q * 16 + j) * AS_STR + nl] = 0.f;
                As_lo[(q * 16 + j) * AS_STR + nl] = 0.f;
                As_hi[(64 + q * 16 + j) * AS_STR + nl] = 0.f;
                As_lo[(64 + q * 16 + j) * AS_STR + nl] = 0.f;
            }
        }
    }
    __syncthreads();

    int warp = tid >> 5, lane = tid & 31;
    int gid = lane >> 2, tig = lane & 3;
    int h0 = warp * 16;                      // 8 warps cover M=128 channels

    float acc[8][4];
#pragma unroll
    for (int nt = 0; nt < 8; nt++)
#pragma unroll
        for (int m = 0; m < 4; m++) acc[nt][m] = 0.f;

    const float* Ah = g_wT_hi + (size_t)(h0 + gid) * 128 + tig;
    const float* Al = g_wT_lo + (size_t)(h0 + gid) * 128 + tig;

#pragma unroll 1
    for (int kk = 0; kk < 16; kk++) {
        int kb = kk * 8;
        unsigned a_hi[4], a_lo[4];
        a_hi[0] = __float_as_uint(Ah[kb]);
        a_hi[1] = __float_as_uint(Ah[kb + 8 * 128]);
        a_hi[2] = __float_as_uint(Ah[kb + 4]);
        a_hi[3] = __float_as_uint(Ah[kb + 8 * 128 + 4]);
        a_lo[0] = __float_as_uint(Al[kb]);
        a_lo[1] = __float_as_uint(Al[kb + 8 * 128]);
        a_lo[2] = __float_as_uint(Al[kb + 4]);
        a_lo[3] = __float_as_uint(Al[kb + 8 * 128 + 4]);
#pragma unroll
        for (int nt = 0; nt < 8; nt++) {
            int n0 = nt * 8;
            unsigned b_hi[2], b_lo[2];
            b_hi[0] = __float_as_uint(As_hi[(kb + tig) * AS_STR + n0 + gid]);
            b_hi[1] = __float_as_uint(As_hi[(kb + tig + 4) * AS_STR + n0 + gid]);
            b_lo[0] = __float_as_uint(As_lo[(kb + tig) * AS_STR + n0 + gid]);
            b_lo[1] = __float_as_uint(As_lo[(kb + tig + 4) * AS_STR + n0 + gid]);
            mma_tf32(acc[nt], a_hi, b_hi);
            mma_tf32(acc[nt], a_lo, b_hi);
            mma_tf32(acc[nt], a_hi, b_lo);
        }
    }

    // epilogue: out[h][n] = acc + staticT[h][n]; accumulate BN sum/sumsq
    int c1 = h0 + gid;        // channel for acc[.][0..1]
    int c2 = c1 + 8;          // channel for acc[.][2..3]
    float s1 = 0.f, q1 = 0.f, s2 = 0.f, q2 = 0.f;
    const float* st1 = g_staticT + (size_t)c1 * NN;
    const float* st2 = g_staticT + (size_t)c2 * NN;
#pragma unroll
    for (int nt = 0; nt < 8; nt++) {
        int n_g = base + nt * 8 + 2 * tig;
        if (n_g + 1 < NN) {
            float2 sa = *(const float2*)(st1 + n_g);
            float2 sb = *(const float2*)(st2 + n_g);
            float v0 = acc[nt][0] + sa.x, v1 = acc[nt][1] + sa.y;
            float v2 = acc[nt][2] + sb.x, v3 = acc[nt][3] + sb.y;
            s1 += v0 + v1; q1 += v0 * v0 + v1 * v1;
            s2 += v2 + v3; q2 += v2 * v2 + v3 * v3;
        } else if (n_g < NN) {
            float v0 = acc[nt][0] + st1[n_g];
            float v2 = acc[nt][2] + st2[n_g];
            s1 += v0; q1 += v0 * v0;
            s2 += v2; q2 += v2 * v2;
        }
    }
    atomicAdd(&st[c1], s1);
    atomicAdd(&st[128 + c1], q1);
    atomicAdd(&st[c2], s2);
    atomicAdd(&st[128 + c2], q2);
    __syncthreads();
    atomicAdd(&g_stats_t[t * 256 + tid], st[tid]);
}

// ---------------- focal rows for ALL t: BN finalize in-block + GEMM + ReLU ----------------
__global__ __launch_bounds__(256)
void focal_all_kernel(const float* __restrict__ x, const int* __restrict__ ptr,
                      const float* __restrict__ gamma, const float* __restrict__ beta) {
    __shared__ __align__(16) float As[128 * 9];
    __shared__ float s_sc[128], s_sh[128];
    int tid = threadIdx.x;
    int t = blockIdx.y;
    int warp = tid >> 5, lane = tid & 31;

    if (tid < 128) {
        float m = g_stats_t[t * 256 + tid] / (float)NN;
        float var = g_stats_t[t * 256 + 128 + tid] / (float)NN - m * m;
        float sc = gamma[tid] * rsqrtf(var + BN_EPS);
        s_sc[tid] = sc;
        s_sh[tid] = beta[tid] - m * sc;
    }
    {
        int b = blockIdx.x * 8 + warp;
        int n = ptr[b];
        const float* xr = x + (size_t)n * (TT * FF) + t * FF;
        const float* ar = g_agg + (size_t)n * (TT * FF) + t * FF;
        As[lane * 9 + warp] = xr[lane];
        As[(lane + 32) * 9 + warp] = xr[lane + 32];
        As[(lane + 64) * 9 + warp] = ar[lane];
        As[(lane + 96) * 9 + warp] = ar[lane + 32];
    }
    __syncthreads();

    int r = warp;
    int c0 = lane * 4;
    float v0 = 0.f, v1 = 0.f, v2 = 0.f, v3 = 0.f;
#pragma unroll 4
    for (int k = 0; k < 128; k++) {
        float a = As[k * 9 + r];
        float4 w = *(const float4*)&g_wcomb[k * HH + c0];
        v0 += a * w.x; v1 += a * w.y; v2 += a * w.z; v3 += a * w.w;
    }
    int b = blockIdx.x * 8 + r;
    int n = ptr[b];
    const float4 sv = *(const float4*)&g_static[(size_t)n * HH + c0];
    v0 += sv.x; v1 += sv.y; v2 += sv.z; v3 += sv.w;
    v0 = fmaxf(fmaf(v0, s_sc[c0 + 0], s_sh[c0 + 0]), 0.f);
    v1 = fmaxf(fmaf(v1, s_sc[c0 + 1], s_sh[c0 + 1]), 0.f);
    v2 = fmaxf(fmaf(v2, s_sc[c0 + 2], s_sh[c0 + 2]), 0.f);
    v3 = fmaxf(fmaf(v3, s_sc[c0 + 3], s_sh[c0 + 3]), 0.f);
    *(float4*)&g_hseq[((size_t)t * BB + b) * HH + c0] = make_float4(v0, v1, v2, v3);
}

// ---------------- fused LSTM step ----------------
__device__ __forceinline__ float sigm(float x) { return 1.f / (1.f + expf(-x)); }

__global__ __launch_bounds__(256)
void lstm_step_kernel(int t, const float* __restrict__ b_ih, const float* __restrict__ b_hh) {
    __shared__ __align__(16) float sm[16 * 516];
    __shared__ float bias[512];
    int tid = threadIdx.x;
    int bb = blockIdx.x * 16;  // grid = 128

    bias[tid] = b_ih[tid] + b_hh[tid];
    bias[tid + 256] = b_ih[tid + 256] + b_hh[tid + 256];

    {
        int row = tid >> 4;
        int kk = tid & 15;
        int b = bb + row;
        const float* hin = &g_hseq[((size_t)t * BB + b) * HH];
        const float* hpr = &g_h[(size_t)b * HH];
#pragma unroll
        for (int m = 0; m < 16; m++) {
            int k = kk + 16 * m;
            sm[k * 17 + row] = (k < HH) ? hin[k] : hpr[k - HH];
        }
    }
    __syncthreads();

    int jg = tid & 31;
    int bg = tid >> 5;
    int j0 = jg * 16;
    unsigned long long acc[2][8];
#pragma unroll
    for (int i = 0; i < 2; i++)
#pragma unroll
        for (int m = 0; m < 8; m++) acc[i][m] = 0ULL;

#pragma unroll 2
    for (int k = 0; k < 256; k++) {
        float a0 = sm[k * 17 + bg * 2];
        float a1 = sm[k * 17 + bg * 2 + 1];
        const ulonglong2* Wp = (const ulonglong2*)&g_wlstm[(size_t)k * 512 + j0];
        ulonglong2 w0 = Wp[0], w1 = Wp[1], w2 = Wp[2], w3 = Wp[3];
        unsigned long long p0 = pk2(a0, a0);
        unsigned long long p1 = pk2(a1, a1);
        acc[0][0] = ffma2(p0, w0.x, acc[0][0]); acc[0][1] = ffma2(p0, w0.y, acc[0][1]);
        acc[0][2] = ffma2(p0, w1.x, acc[0][2]); acc[0][3] = ffma2(p0, w1.y, acc[0][3]);
        acc[0][4] = ffma2(p0, w2.x, acc[0][4]); acc[0][5] = ffma2(p0, w2.y, acc[0][5]);
        acc[0][6] = ffma2(p0, w3.x, acc[0][6]); acc[0][7] = ffma2(p0, w3.y, acc[0][7]);
        acc[1][0] = ffma2(p1, w0.x, acc[1][0]); acc[1][1] = ffma2(p1, w0.y, acc[1][1]);
        acc[1][2] = ffma2(p1, w1.x, acc[1][2]); acc[1][3] = ffma2(p1, w1.y, acc[1][3]);
        acc[1][4] = ffma2(p1, w2.x, acc[1][4]); acc[1][5] = ffma2(p1, w2.y, acc[1][5]);
        acc[1][6] = ffma2(p1, w3.x, acc[1][6]); acc[1][7] = ffma2(p1, w3.y, acc[1][7]);
    }
    __syncthreads();

#pragma unroll
    for (int i = 0; i < 2; i++) {
        int row = bg * 2 + i;
        float v[16];
#pragma unroll
        for (int m = 0; m < 8; m++) upk2(acc[i][m], v[2 * m], v[2 * m + 1]);
#pragma unroll
        for (int m = 0; m < 16; m++) sm[row * 516 + j0 + m] = v[m];
    }
    __syncthreads();

#pragma unroll
    for (int m = 0; m < 8; m++) {
        int gid = tid + 256 * m;
        int r = gid >> 7, h = gid & 127;
        const float* gr = &sm[r * 516];
        float gi = gr[h]       + bias[h];
        float gf = gr[128 + h] + bias[128 + h];
        float gg = gr[256 + h] + bias[256 + h];
        float go = gr[384 + h] + bias[384 + h];
        float i_ = sigm(gi), f_ = sigm(gf), o_ = sigm(go);
        float g_ = tanhf(gg);
        size_t gix = (size_t)(bb + r) * HH + h;
        float c = f_ * g_c[gix] + i_ * g_;
        g_c[gix] = c;
        g_h[gix] = o_ * tanhf(c);
    }
}

// ---------------- classifier ----------------
__global__ void cls_kernel(const float* __restrict__ w_cls, const float* __restrict__ b_cls,
                           float* __restrict__ out) {
    int idx = blockIdx.x * 256 + threadIdx.x;
    int b = idx >> 1, c = idx & 1;
    float s = b_cls[c];
    const float* hr = &g_h[(size_t)b * HH];
#pragma unroll 8
    for (int k = 0; k < HH; k++) s += hr[k] * w_cls[k * CC + c];
    out[idx] = s;
}

// ---------------- launch ----------------
#define SAGE_SMEM ((2 * 128 * AS_STR + 256) * 4)

extern "C" void kernel_launch(void* const* d_in, const int* in_sizes, int n_in,
                              void* d_out, int out_size) {
    const float* x      = (const float*)d_in[0];
    const int*   ei     = (const int*)d_in[1];     // int32 (JAX x64 disabled)
    const float* eattr  = (const float*)d_in[2];
    const int*   ptr    = (const int*)d_in[3];     // int32
    const float* w_msg  = (const float*)d_in[4];
    const float* b_msg  = (const float*)d_in[5];
    const float* w_self = (const float*)d_in[6];
    const float* b_self = (const float*)d_in[7];
    const float* gamma  = (const float*)d_in[8];
    const float* beta   = (const float*)d_in[9];
    const float* w_ih   = (const float*)d_in[10];
    const float* w_hh   = (const float*)d_in[11];
    const float* b_ih   = (const float*)d_in[12];
    const float* b_hh   = (const float*)d_in[13];
    const float* w_cls  = (const float*)d_in[14];
    const float* b_cls  = (const float*)d_in[15];
    float* out = (float*)d_out;

    static int smem_set = 0;
    if (!smem_set) {
        cudaFuncSetAttribute(sage_tc_kernel, cudaFuncAttributeMaxDynamicSharedMemorySize, SAGE_SMEM);
        smem_set = 1;
    }

    void *p_deg, *p_cur, *p_ea, *p_h, *p_c, *p_st;
    cudaGetSymbolAddress(&p_deg, g_deg);
    cudaGetSymbolAddress(&p_cur, g_cursor);
    cudaGetSymbolAddress(&p_ea,  g_eattr);
    cudaGetSymbolAddress(&p_h,   g_h);
    cudaGetSymbolAddress(&p_c,   g_c);
    cudaGetSymbolAddress(&p_st,  g_stats_t);
    cudaMemsetAsync(p_deg, 0, NN * sizeof(int));
    cudaMemsetAsync(p_cur, 0, NN * sizeof(int));
    cudaMemsetAsync(p_ea,  0, NN * EDD * sizeof(float));
    cudaMemsetAsync(p_h,   0, BB * HH * sizeof(float));
    cudaMemsetAsync(p_c,   0, BB * HH * sizeof(float));
    cudaMemsetAsync(p_st,  0, TT * 2 * HH * sizeof(float));

    edge_prep_kernel<<<EE / 256, 256>>>(ei, eattr);      // k1
    scan_kernel<<<1, 1024>>>();                          // k2
    fill_kernel<<<EE / 256, 256>>>(ei);                  // k3
    gather5_kernel<<<NN / 8, 256>>>(x, 0);               // k4
    gather5_kernel<<<NN / 8, 256>>>(x, 5);               // k5
    static_kernel<<<(NN * HH) / 256, 256>>>(w_msg, b_msg, b_self);  // k6
    wcomb_kernel<<<(128 * 128) / 256, 256>>>(w_self, w_msg);
    wlstm_kernel<<<(256 * 512) / 256, 256>>>(w_ih, w_hh);

    dim3 sg((NN + 63) / 64, TT);                         // 1563 x 10
    sage_tc_kernel<<<sg, 256, SAGE_SMEM>>>(x);
    dim3 fg(BB / 8, TT);                                 // 256 x 10
    focal_all_kernel<<<fg, 256>>>(x, ptr, gamma, beta);

    for (int t = 0; t < TT; t++)
        lstm_step_kernel<<<BB / 16, 256>>>(t, b_ih, b_hh);
    cls_kernel<<<(BB * CC) / 256, 256>>>(w_cls, b_cls, out);
}